// round 8
// baseline (speedup 1.0000x reference)
#include <cuda_runtime.h>
#include <cuda_bf16.h>
#include <cstdint>

#define N_NODES 100000
#define DIM 128
#define NNZ 1600000
#define NBLK ((N_NODES + 255) / 256)   // 391 scan blocks

// -------- device-global scratch (no allocations allowed) --------
__device__ float g_x[(size_t)N_NODES * DIM];             // current layer embedding (f32)
__device__ __nv_bfloat16 g_ah[(size_t)N_NODES * 256];    // A hi: [0:128)=side+x, [128:256)=side*x
__device__ __nv_bfloat16 g_al[(size_t)N_NODES * 256];    // A lo
__device__ __nv_bfloat16 g_wbh[2 * 256 * 128];           // pre-split weights hi, k-major [layer][k][n]
__device__ __nv_bfloat16 g_wbl[2 * 256 * 128];           // pre-split weights lo
__device__ float g_bias[2 * 128];                         // combined bias per layer
__device__ int   g_cnt[N_NODES];                          // CSR histogram
__device__ int   g_bsum[NBLK];                            // per-block sums
__device__ int   g_boff[NBLK];                            // per-block exclusive offsets
__device__ int   g_ptr[N_NODES + 1];                      // CSR row pointers
__device__ int   g_wptr[N_NODES];                         // scatter cursors
__device__ int   g_scol[NNZ];                             // sorted cols
__device__ float g_sval[NNZ];                             // sorted vals

__device__ __forceinline__ void bf16_split(float v, __nv_bfloat16& h, __nv_bfloat16& l) {
    h = __float2bfloat16(v);
    l = __float2bfloat16(v - __bfloat162float(h));
}

// ================= init: x = emb, out[:,0:128] = emb, cnt = 0 =================
__global__ void __launch_bounds__(256) init_kernel(const float* __restrict__ emb,
                                                   float* __restrict__ out) {
    int fi = blockIdx.x * blockDim.x + threadIdx.x;   // float4 index
    if (fi < N_NODES) g_cnt[fi] = 0;
    if (fi >= N_NODES * 32) return;
    int row = fi >> 5;
    int c   = fi & 31;
    float4 e = ((const float4*)emb)[fi];
    ((float4*)g_x)[fi] = e;
    ((float4*)out)[row * 96 + c] = e;                 // 384 floats = 96 float4 per row
}

// ================= weight prep: split + transpose both layers, once =================
__global__ void __launch_bounds__(256) wprep_kernel(const float* __restrict__ W1,
                                                    const float* __restrict__ b1,
                                                    const float* __restrict__ W2,
                                                    const float* __restrict__ b2) {
    int idx = blockIdx.x * blockDim.x + threadIdx.x;   // [layer(1)][k(8)][n(7)] = 2^16
    if (idx >= 2 * 256 * 128) return;
    int n = idx & 127;
    int k = (idx >> 7) & 255;
    int layer = idx >> 15;
    float w = (k < 128) ? W1[layer * 16384 + n * 128 + k]
                        : W2[layer * 16384 + n * 128 + (k - 128)];
    __nv_bfloat16 h, l;
    bf16_split(w, h, l);
    g_wbh[idx] = h;
    g_wbl[idx] = l;
    if (idx < 256) {
        int L = idx >> 7, nn = idx & 127;
        g_bias[idx] = b1[L * 128 + nn] + b2[L * 128 + nn];
    }
}

// ================= CSR build =================
__global__ void __launch_bounds__(256) hist_kernel(const int* __restrict__ rows) {
    int e = blockIdx.x * blockDim.x + threadIdx.x;
    if (e < NNZ) atomicAdd(&g_cnt[rows[e]], 1);
}

// phase 1: per-block sums of 256 counters
__global__ void __launch_bounds__(256) bsum_kernel() {
    int g = blockIdx.x * 256 + threadIdx.x;
    int v = (g < N_NODES) ? g_cnt[g] : 0;
#pragma unroll
    for (int d = 16; d > 0; d >>= 1) v += __shfl_xor_sync(0xffffffffu, v, d);
    __shared__ int ws[8];
    if ((threadIdx.x & 31) == 0) ws[threadIdx.x >> 5] = v;
    __syncthreads();
    if (threadIdx.x == 0) {
        int s = 0;
#pragma unroll
        for (int i = 0; i < 8; i++) s += ws[i];
        g_bsum[blockIdx.x] = s;
    }
}

// phase 2: single-block exclusive scan of NBLK block sums (NBLK=391 <= 512)
__global__ void __launch_bounds__(512) bscan_kernel() {
    int t = threadIdx.x;
    int lane = t & 31, warp = t >> 5;
    int v = (t < NBLK) ? g_bsum[t] : 0;
    int s = v;
#pragma unroll
    for (int d = 1; d < 32; d <<= 1) {
        int u = __shfl_up_sync(0xffffffffu, s, d);
        if (lane >= d) s += u;
    }
    __shared__ int ws[16];
    if (lane == 31) ws[warp] = s;
    __syncthreads();
    if (warp == 0) {                          // ALL 32 lanes participate in the shuffles
        int w = (lane < 16) ? ws[lane] : 0;
#pragma unroll
        for (int d = 1; d < 32; d <<= 1) {
            int u = __shfl_up_sync(0xffffffffu, w, d);
            if (lane >= d) w += u;
        }
        if (lane < 16) ws[lane] = w;
    }
    __syncthreads();
    int excl = s - v + (warp > 0 ? ws[warp - 1] : 0);
    if (t < NBLK) g_boff[t] = excl;
}

// phase 3: block-local exclusive scan + global offset -> g_ptr / g_wptr
__global__ void __launch_bounds__(256) pscan_kernel() {
    int t = threadIdx.x;
    int lane = t & 31, warp = t >> 5;
    int g = blockIdx.x * 256 + t;
    int v = (g < N_NODES) ? g_cnt[g] : 0;
    int s = v;
#pragma unroll
    for (int d = 1; d < 32; d <<= 1) {
        int u = __shfl_up_sync(0xffffffffu, s, d);
        if (lane >= d) s += u;
    }
    __shared__ int ws[8];
    if (lane == 31) ws[warp] = s;
    __syncthreads();
    if (warp == 0) {                          // ALL 32 lanes participate in the shuffles
        int w = (lane < 8) ? ws[lane] : 0;
#pragma unroll
        for (int d = 1; d < 32; d <<= 1) {
            int u = __shfl_up_sync(0xffffffffu, w, d);
            if (lane >= d) w += u;
        }
        if (lane < 8) ws[lane] = w;
    }
    __syncthreads();
    int excl = s - v + (warp > 0 ? ws[warp - 1] : 0) + g_boff[blockIdx.x];
    if (g < N_NODES) {
        g_ptr[g]  = excl;
        g_wptr[g] = excl;
        if (g == N_NODES - 1) g_ptr[N_NODES] = NNZ;
    }
}

__global__ void __launch_bounds__(256) scatter_kernel(const int* __restrict__ rows,
                                                      const int* __restrict__ cols,
                                                      const float* __restrict__ vals) {
    int e = blockIdx.x * blockDim.x + threadIdx.x;
    if (e >= NNZ) return;
    int pos = atomicAdd(&g_wptr[rows[e]], 1);
    g_scol[pos] = cols[e];
    g_sval[pos] = vals[e];
}

// ================= gather SpMM + fused bf16-split A generation =================
// warp per row; edge loop unrolled 4-wide for MLP (independent x-row loads in flight)
__global__ void __launch_bounds__(256) gather_kernel() {
    int gid  = blockIdx.x * blockDim.x + threadIdx.x;
    int r    = gid >> 5;
    int lane = gid & 31;
    if (r >= N_NODES) return;
    int n0 = g_ptr[r], n1 = g_ptr[r + 1];
    const float4* gx4 = (const float4*)g_x;
    float4 acc = make_float4(0.f, 0.f, 0.f, 0.f);

    int e = n0;
    for (; e + 4 <= n1; e += 4) {
        int   c0 = __ldg(&g_scol[e]),     c1 = __ldg(&g_scol[e + 1]);
        int   c2 = __ldg(&g_scol[e + 2]), c3 = __ldg(&g_scol[e + 3]);
        float v0 = __ldg(&g_sval[e]),     v1 = __ldg(&g_sval[e + 1]);
        float v2 = __ldg(&g_sval[e + 2]), v3 = __ldg(&g_sval[e + 3]);
        float4 x0 = gx4[(size_t)c0 * 32 + lane];
        float4 x1 = gx4[(size_t)c1 * 32 + lane];
        float4 x2 = gx4[(size_t)c2 * 32 + lane];
        float4 x3 = gx4[(size_t)c3 * 32 + lane];
        acc.x = fmaf(v0, x0.x, acc.x); acc.y = fmaf(v0, x0.y, acc.y);
        acc.z = fmaf(v0, x0.z, acc.z); acc.w = fmaf(v0, x0.w, acc.w);
        acc.x = fmaf(v1, x1.x, acc.x); acc.y = fmaf(v1, x1.y, acc.y);
        acc.z = fmaf(v1, x1.z, acc.z); acc.w = fmaf(v1, x1.w, acc.w);
        acc.x = fmaf(v2, x2.x, acc.x); acc.y = fmaf(v2, x2.y, acc.y);
        acc.z = fmaf(v2, x2.z, acc.z); acc.w = fmaf(v2, x2.w, acc.w);
        acc.x = fmaf(v3, x3.x, acc.x); acc.y = fmaf(v3, x3.y, acc.y);
        acc.z = fmaf(v3, x3.z, acc.z); acc.w = fmaf(v3, x3.w, acc.w);
    }
    for (; e < n1; e++) {
        int   c = __ldg(&g_scol[e]);
        float v = __ldg(&g_sval[e]);
        float4 xc = gx4[(size_t)c * 32 + lane];
        acc.x = fmaf(v, xc.x, acc.x);
        acc.y = fmaf(v, xc.y, acc.y);
        acc.z = fmaf(v, xc.z, acc.z);
        acc.w = fmaf(v, xc.w, acc.w);
    }

    float4 xr = gx4[(size_t)r * 32 + lane];
    float a[4] = {acc.x + xr.x, acc.y + xr.y, acc.z + xr.z, acc.w + xr.w};
    float b[4] = {acc.x * xr.x, acc.y * xr.y, acc.z * xr.z, acc.w * xr.w};
    __nv_bfloat16 ha[4], la[4], hb[4], lb[4];
#pragma unroll
    for (int j = 0; j < 4; j++) { bf16_split(a[j], ha[j], la[j]); bf16_split(b[j], hb[j], lb[j]); }
    size_t base = (size_t)r * 256 + lane * 4;
    *(uint2*)(g_ah + base)        = *(uint2*)ha;
    *(uint2*)(g_ah + base + 128)  = *(uint2*)hb;
    *(uint2*)(g_al + base)        = *(uint2*)la;
    *(uint2*)(g_al + base + 128)  = *(uint2*)lb;
}

// ==================== mma.sync / cp.async helpers (baseline ISA) ====================
__device__ __forceinline__ uint32_t smem_u32(const void* p) {
    uint32_t a;
    asm("{ .reg .u64 t; cvta.to.shared.u64 t, %1; cvt.u32.u64 %0, t; }" : "=r"(a) : "l"(p));
    return a;
}
__device__ __forceinline__ void ldsm_x4(uint32_t* r, uint32_t addr) {
    asm volatile("ldmatrix.sync.aligned.m8n8.x4.shared.b16 {%0,%1,%2,%3}, [%4];"
                 : "=r"(r[0]), "=r"(r[1]), "=r"(r[2]), "=r"(r[3]) : "r"(addr));
}
__device__ __forceinline__ void ldsm_x4_t(uint32_t* r, uint32_t addr) {
    asm volatile("ldmatrix.sync.aligned.m8n8.x4.trans.shared.b16 {%0,%1,%2,%3}, [%4];"
                 : "=r"(r[0]), "=r"(r[1]), "=r"(r[2]), "=r"(r[3]) : "r"(addr));
}
__device__ __forceinline__ void mma_bf16(float* d, const uint32_t* a, const uint32_t* b) {
    asm volatile("mma.sync.aligned.m16n8k16.row.col.f32.bf16.bf16.f32 "
                 "{%0,%1,%2,%3}, {%4,%5,%6,%7}, {%8,%9}, {%0,%1,%2,%3};"
                 : "+f"(d[0]), "+f"(d[1]), "+f"(d[2]), "+f"(d[3])
                 : "r"(a[0]), "r"(a[1]), "r"(a[2]), "r"(a[3]), "r"(b[0]), "r"(b[1]));
}
__device__ __forceinline__ void cp16(uint32_t dst, const void* src, bool pred) {
    asm volatile("cp.async.cg.shared.global [%0], [%1], 16, %2;"
                 :: "r"(dst), "l"(src), "r"(pred ? 16u : 0u));
}
__device__ __forceinline__ void cp_commit() {
    asm volatile("cp.async.commit_group;" ::: "memory");
}

// ================= pipelined bf16-split tensor-core fused dense layer =================
#define RSTRIDE_B 272
#define ASTRIDE 144
#define OFF_BH 0
#define OFF_BL (256 * RSTRIDE_B)                        // 69632
#define OFF_A  (2 * 256 * RSTRIDE_B)                    // 139264
#define ABUF(m, b) (OFF_A + (((b) * 2 + (m)) * 128 * ASTRIDE))
#define OFF_C  OFF_A                                    // 128*132*4 = 67584 <= 73728
#define GEMM_SMEM (OFF_A + 4 * 128 * ASTRIDE)           // 212992

__global__ void __launch_bounds__(256, 1) mma_gemm_kernel(float* __restrict__ out, int layer) {
    extern __shared__ char smem[];
    uint32_t sbase = smem_u32(smem);
    int tid = threadIdx.x;
    int wid = tid >> 5, lid = tid & 31;
    int warp_m = wid >> 2, warp_n = wid & 3;      // 2x4 warp grid: 64-row x 32-col warp tiles
    int row0 = blockIdx.x * 128;

    // ---- issue B staging (group 0): pure async copy of pre-split weights ----
    {
        const char* gwh = (const char*)g_wbh + (size_t)layer * 65536;
        const char* gwl = (const char*)g_wbl + (size_t)layer * 65536;
        for (int i = tid; i < 8192; i += 256) {
            int m = i >> 12, rem = i & 4095, r = rem >> 4, q = rem & 15;
            uint32_t dst = sbase + (m ? OFF_BL : OFF_BH) + r * RSTRIDE_B + q * 16;
            const char* src = (m ? gwl : gwh) + r * 256 + q * 16;
            cp16(dst, src, true);
        }
        cp_commit();
    }

    // ---- A chunk staging (async) ----
    auto stageA = [&](int c) {
        int buf = c & 1;
        const char* gah = (const char*)g_ah;
        const char* gal = (const char*)g_al;
#pragma unroll
        for (int it = 0; it < 8; it++) {
            int i = tid + it * 256;                // 0..2047
            int m = i >> 10, rem = i & 1023, r = rem >> 3, q = rem & 7;
            int gr = row0 + r;
            uint32_t dst = sbase + ABUF(m, buf) + r * ASTRIDE + q * 16;
            const char* src = (m ? gal : gah) + (size_t)gr * 512 + c * 128 + q * 16;
            cp16(dst, src, gr < N_NODES);
        }
        cp_commit();
    };
    stageA(0);   // group 1
    stageA(1);   // group 2

    float acc[4][4][4];
#pragma unroll
    for (int mf = 0; mf < 4; mf++)
#pragma unroll
        for (int nf = 0; nf < 4; nf++)
#pragma unroll
            for (int q = 0; q < 4; q++) acc[mf][nf][q] = 0.f;

    // ---- pipelined chunk loop ----
#pragma unroll
    for (int c = 0; c < 4; c++) {
        if (c < 3) asm volatile("cp.async.wait_group 1;" ::: "memory");
        else       asm volatile("cp.async.wait_group 0;" ::: "memory");
        __syncthreads();

        int buf = c & 1;
        int kb = c * 64;
#pragma unroll
        for (int k16 = 0; k16 < 4; k16++) {
            int k0 = k16 * 16;
            uint32_t ah[4][4], al[4][4];
            int ar = (lid & 15);
            int ac = (k0 + ((lid >> 4) << 3)) * 2;
#pragma unroll
            for (int mf = 0; mf < 4; mf++) {
                int r = warp_m * 64 + mf * 16 + ar;
                ldsm_x4(ah[mf], sbase + ABUF(0, buf) + r * ASTRIDE + ac);
                ldsm_x4(al[mf], sbase + ABUF(1, buf) + r * ASTRIDE + ac);
            }
            uint32_t bh[4][2], bl[4][2];
            int br = kb + k0 + (lid & 15);
#pragma unroll
            for (int np = 0; np < 2; np++) {
                int nc = (warp_n * 32 + np * 16 + ((lid >> 4) << 3)) * 2;
                uint32_t t[4];
                ldsm_x4_t(t, sbase + OFF_BH + br * RSTRIDE_B + nc);
                bh[np * 2][0] = t[0]; bh[np * 2][1] = t[1];
                bh[np * 2 + 1][0] = t[2]; bh[np * 2 + 1][1] = t[3];
                ldsm_x4_t(t, sbase + OFF_BL + br * RSTRIDE_B + nc);
                bl[np * 2][0] = t[0]; bl[np * 2][1] = t[1];
                bl[np * 2 + 1][0] = t[2]; bl[np * 2 + 1][1] = t[3];
            }
#pragma unroll
            for (int mf = 0; mf < 4; mf++)
#pragma unroll
                for (int nf = 0; nf < 4; nf++) {
                    mma_bf16(acc[mf][nf], ah[mf], bh[nf]);  // hi*hi
                    mma_bf16(acc[mf][nf], ah[mf], bl[nf]);  // hi*lo
                    mma_bf16(acc[mf][nf], al[mf], bh[nf]);  // lo*hi
                }
        }
        __syncthreads();           // all ldmatrix reads of this buffer done
        if (c + 2 < 4) stageA(c + 2);
    }
    __syncthreads();               // last chunk reads complete -> safe to alias C over A

    // ---- dump accumulators to SMEM C tile ----
    float* Cs = (float*)(smem + OFF_C);
#pragma unroll
    for (int mf = 0; mf < 4; mf++)
#pragma unroll
        for (int nf = 0; nf < 4; nf++) {
            int r = warp_m * 64 + mf * 16 + (lid >> 2);
            int cc = warp_n * 32 + nf * 8 + (lid & 3) * 2;
            *(float2*)&Cs[r * 132 + cc]       = make_float2(acc[mf][nf][0], acc[mf][nf][1]);
            *(float2*)&Cs[(r + 8) * 132 + cc] = make_float2(acc[mf][nf][2], acc[mf][nf][3]);
        }
    __syncthreads();

    // ---- epilogue: warp per row — bias + leaky + L2 norm + dual store ----
    float4 bias4 = ((const float4*)(g_bias + layer * 128))[lid];
#pragma unroll
    for (int it = 0; it < 16; it++) {
        int row = it * 8 + wid;
        int gr = row0 + row;
        float4 v = *(float4*)&Cs[row * 132 + lid * 4];
        float t0 = v.x + bias4.x, t1 = v.y + bias4.y;
        float t2 = v.z + bias4.z, t3 = v.w + bias4.w;
        t0 = (t0 > 0.f) ? t0 : 0.01f * t0;
        t1 = (t1 > 0.f) ? t1 : 0.01f * t1;
        t2 = (t2 > 0.f) ? t2 : 0.01f * t2;
        t3 = (t3 > 0.f) ? t3 : 0.01f * t3;
        float ss = fmaf(t0, t0, fmaf(t1, t1, fmaf(t2, t2, t3 * t3)));
        ss += __shfl_xor_sync(0xffffffffu, ss, 16);
        ss += __shfl_xor_sync(0xffffffffu, ss, 8);
        ss += __shfl_xor_sync(0xffffffffu, ss, 4);
        ss += __shfl_xor_sync(0xffffffffu, ss, 2);
        ss += __shfl_xor_sync(0xffffffffu, ss, 1);
        float sc = 1.0f / fmaxf(sqrtf(ss), 1e-12f);
        if (gr < N_NODES) {
            float4 o = make_float4(t0 * sc, t1 * sc, t2 * sc, t3 * sc);
            ((float4*)&g_x[(size_t)gr * 128])[lid] = o;
            ((float4*)&out[(size_t)gr * 384 + (size_t)(layer + 1) * 128])[lid] = o;
        }
    }
}

// ================= launch =================
extern "C" void kernel_launch(void* const* d_in, const int* in_sizes, int n_in,
                              void* d_out, int out_size) {
    const int*   adj_row  = (const int*)d_in[0];
    const int*   adj_col  = (const int*)d_in[1];
    const float* adj_vals = (const float*)d_in[2];
    const float* emb      = (const float*)d_in[3];
    const float* W1w      = (const float*)d_in[4];
    const float* W1b      = (const float*)d_in[5];
    const float* W2w      = (const float*)d_in[6];
    const float* W2b      = (const float*)d_in[7];
    float* out = (float*)d_out;

    cudaFuncSetAttribute(mma_gemm_kernel, cudaFuncAttributeMaxDynamicSharedMemorySize, GEMM_SMEM);

    init_kernel<<<(N_NODES * 32 + 255) / 256, 256>>>(emb, out);
    wprep_kernel<<<(2 * 256 * 128 + 255) / 256, 256>>>(W1w, W1b, W2w, W2b);
    hist_kernel<<<(NNZ + 255) / 256, 256>>>(adj_row);
    bsum_kernel<<<NBLK, 256>>>();
    bscan_kernel<<<1, 512>>>();
    pscan_kernel<<<NBLK, 256>>>();
    scatter_kernel<<<(NNZ + 255) / 256, 256>>>(adj_row, adj_col, adj_vals);

    const int gather_blocks = (N_NODES * 32 + 255) / 256;   // warp per row
    const int gemm_blocks = (N_NODES + 127) / 128;          // 782

    for (int layer = 0; layer < 2; layer++) {
        gather_kernel<<<gather_blocks, 256>>>();
        mma_gemm_kernel<<<gemm_blocks, 256, GEMM_SMEM>>>(out, layer);
    }
}

// round 9
// speedup vs baseline: 1.0712x; 1.0712x over previous
#include <cuda_runtime.h>
#include <cuda_bf16.h>
#include <cstdint>

#define N_NODES 100000
#define DIM 128
#define NNZ 1600000
#define NBLK ((N_NODES + 255) / 256)   // 391 scan blocks
#define N_TILES ((N_NODES + 127) / 128) // 782 gemm tiles
#define GEMM_GRID 152                   // persistent blocks (GB300: 152 SMs)

// -------- device-global scratch (no allocations allowed) --------
__device__ float g_x[(size_t)N_NODES * DIM];             // current layer embedding (f32)
__device__ __nv_bfloat16 g_ah[(size_t)N_NODES * 256];    // A hi: [0:128)=side+x, [128:256)=side*x
__device__ __nv_bfloat16 g_al[(size_t)N_NODES * 256];    // A lo
__device__ __nv_bfloat16 g_wbh[2 * 256 * 128];           // pre-split weights hi, k-major [layer][k][n]
__device__ __nv_bfloat16 g_wbl[2 * 256 * 128];           // pre-split weights lo
__device__ float g_bias[2 * 128];                         // combined bias per layer
__device__ int   g_cnt[N_NODES];                          // CSR histogram (zeroed by pscan after use)
__device__ int   g_bsum[NBLK];                            // per-block sums
__device__ int   g_boff[NBLK];                            // per-block exclusive offsets
__device__ int   g_ptr[N_NODES + 1];                      // CSR row pointers
__device__ int   g_wptr[N_NODES];                         // scatter cursors
__device__ int2  g_edge[NNZ];                             // packed (col, val) sorted by row

__device__ __forceinline__ void bf16_split(float v, __nv_bfloat16& h, __nv_bfloat16& l) {
    h = __float2bfloat16(v);
    l = __float2bfloat16(v - __bfloat162float(h));
}

// ================= fused setup: init-x/out + weight prep + histogram =================
// g_cnt is zero at first launch (static init) and re-zeroed by pscan each run,
// so hist can run concurrently with init (no ordering needed between ranges).
#define INIT_N (N_NODES * 32)           // 3,200,000 float4 copies
#define WP_N   (2 * 256 * 128)          // 65,536 weight elements
#define SETUP_N (INIT_N + WP_N + NNZ)

__global__ void __launch_bounds__(256) setup_kernel(const float* __restrict__ emb,
                                                    float* __restrict__ out,
                                                    const float* __restrict__ W1,
                                                    const float* __restrict__ b1,
                                                    const float* __restrict__ W2,
                                                    const float* __restrict__ b2,
                                                    const int* __restrict__ rows) {
    int t = blockIdx.x * blockDim.x + threadIdx.x;
    if (t < INIT_N) {                                  // ---- init ----
        int row = t >> 5, c = t & 31;
        float4 e = ((const float4*)emb)[t];
        ((float4*)g_x)[t] = e;
        ((float4*)out)[row * 96 + c] = e;
    } else if (t < INIT_N + WP_N) {                    // ---- weight prep ----
        int idx = t - INIT_N;
        int n = idx & 127;
        int k = (idx >> 7) & 255;
        int layer = idx >> 15;
        float w = (k < 128) ? W1[layer * 16384 + n * 128 + k]
                            : W2[layer * 16384 + n * 128 + (k - 128)];
        __nv_bfloat16 h, l;
        bf16_split(w, h, l);
        g_wbh[idx] = h;
        g_wbl[idx] = l;
        if (idx < 256) {
            int L = idx >> 7, nn = idx & 127;
            g_bias[idx] = b1[L * 128 + nn] + b2[L * 128 + nn];
        }
    } else if (t < SETUP_N) {                          // ---- histogram ----
        int e = t - (INIT_N + WP_N);
        atomicAdd(&g_cnt[rows[e]], 1);
    }
}

// ================= CSR scan (3 phases) =================
__global__ void __launch_bounds__(256) bsum_kernel() {
    int g = blockIdx.x * 256 + threadIdx.x;
    int v = (g < N_NODES) ? g_cnt[g] : 0;
#pragma unroll
    for (int d = 16; d > 0; d >>= 1) v += __shfl_xor_sync(0xffffffffu, v, d);
    __shared__ int ws[8];
    if ((threadIdx.x & 31) == 0) ws[threadIdx.x >> 5] = v;
    __syncthreads();
    if (threadIdx.x == 0) {
        int s = 0;
#pragma unroll
        for (int i = 0; i < 8; i++) s += ws[i];
        g_bsum[blockIdx.x] = s;
    }
}

__global__ void __launch_bounds__(512) bscan_kernel() {
    int t = threadIdx.x;
    int lane = t & 31, warp = t >> 5;
    int v = (t < NBLK) ? g_bsum[t] : 0;
    int s = v;
#pragma unroll
    for (int d = 1; d < 32; d <<= 1) {
        int u = __shfl_up_sync(0xffffffffu, s, d);
        if (lane >= d) s += u;
    }
    __shared__ int ws[16];
    if (lane == 31) ws[warp] = s;
    __syncthreads();
    if (warp == 0) {                          // all 32 lanes shuffle
        int w = (lane < 16) ? ws[lane] : 0;
#pragma unroll
        for (int d = 1; d < 32; d <<= 1) {
            int u = __shfl_up_sync(0xffffffffu, w, d);
            if (lane >= d) w += u;
        }
        if (lane < 16) ws[lane] = w;
    }
    __syncthreads();
    int excl = s - v + (warp > 0 ? ws[warp - 1] : 0);
    if (t < NBLK) g_boff[t] = excl;
}

__global__ void __launch_bounds__(256) pscan_kernel() {
    int t = threadIdx.x;
    int lane = t & 31, warp = t >> 5;
    int g = blockIdx.x * 256 + t;
    int v = (g < N_NODES) ? g_cnt[g] : 0;
    int s = v;
#pragma unroll
    for (int d = 1; d < 32; d <<= 1) {
        int u = __shfl_up_sync(0xffffffffu, s, d);
        if (lane >= d) s += u;
    }
    __shared__ int ws[8];
    if (lane == 31) ws[warp] = s;
    __syncthreads();
    if (warp == 0) {                          // all 32 lanes shuffle
        int w = (lane < 8) ? ws[lane] : 0;
#pragma unroll
        for (int d = 1; d < 32; d <<= 1) {
            int u = __shfl_up_sync(0xffffffffu, w, d);
            if (lane >= d) w += u;
        }
        if (lane < 8) ws[lane] = w;
    }
    __syncthreads();
    int excl = s - v + (warp > 0 ? ws[warp - 1] : 0) + g_boff[blockIdx.x];
    if (g < N_NODES) {
        g_ptr[g]  = excl;
        g_wptr[g] = excl;
        g_cnt[g]  = 0;                        // reset for next graph replay
        if (g == N_NODES - 1) g_ptr[N_NODES] = NNZ;
    }
}

__global__ void __launch_bounds__(256) scatter_kernel(const int* __restrict__ rows,
                                                      const int* __restrict__ cols,
                                                      const float* __restrict__ vals) {
    int e = blockIdx.x * blockDim.x + threadIdx.x;
    if (e >= NNZ) return;
    int pos = atomicAdd(&g_wptr[rows[e]], 1);
    g_edge[pos] = make_int2(cols[e], __float_as_int(vals[e]));
}

// ================= gather SpMM + fused bf16-split A generation =================
__global__ void __launch_bounds__(256) gather_kernel() {
    int gid  = blockIdx.x * blockDim.x + threadIdx.x;
    int r    = gid >> 5;
    int lane = gid & 31;
    if (r >= N_NODES) return;
    int n0 = g_ptr[r], n1 = g_ptr[r + 1];
    const float4* gx4 = (const float4*)g_x;
    float4 acc = make_float4(0.f, 0.f, 0.f, 0.f);

    int e = n0;
    for (; e + 4 <= n1; e += 4) {
        int2 e0 = __ldg(&g_edge[e]),     e1 = __ldg(&g_edge[e + 1]);
        int2 e2 = __ldg(&g_edge[e + 2]), e3 = __ldg(&g_edge[e + 3]);
        float4 x0 = gx4[(size_t)e0.x * 32 + lane];
        float4 x1 = gx4[(size_t)e1.x * 32 + lane];
        float4 x2 = gx4[(size_t)e2.x * 32 + lane];
        float4 x3 = gx4[(size_t)e3.x * 32 + lane];
        float v0 = __int_as_float(e0.y), v1 = __int_as_float(e1.y);
        float v2 = __int_as_float(e2.y), v3 = __int_as_float(e3.y);
        acc.x = fmaf(v0, x0.x, acc.x); acc.y = fmaf(v0, x0.y, acc.y);
        acc.z = fmaf(v0, x0.z, acc.z); acc.w = fmaf(v0, x0.w, acc.w);
        acc.x = fmaf(v1, x1.x, acc.x); acc.y = fmaf(v1, x1.y, acc.y);
        acc.z = fmaf(v1, x1.z, acc.z); acc.w = fmaf(v1, x1.w, acc.w);
        acc.x = fmaf(v2, x2.x, acc.x); acc.y = fmaf(v2, x2.y, acc.y);
        acc.z = fmaf(v2, x2.z, acc.z); acc.w = fmaf(v2, x2.w, acc.w);
        acc.x = fmaf(v3, x3.x, acc.x); acc.y = fmaf(v3, x3.y, acc.y);
        acc.z = fmaf(v3, x3.z, acc.z); acc.w = fmaf(v3, x3.w, acc.w);
    }
    for (; e < n1; e++) {
        int2 ed = __ldg(&g_edge[e]);
        float v = __int_as_float(ed.y);
        float4 xc = gx4[(size_t)ed.x * 32 + lane];
        acc.x = fmaf(v, xc.x, acc.x);
        acc.y = fmaf(v, xc.y, acc.y);
        acc.z = fmaf(v, xc.z, acc.z);
        acc.w = fmaf(v, xc.w, acc.w);
    }

    float4 xr = gx4[(size_t)r * 32 + lane];
    float a[4] = {acc.x + xr.x, acc.y + xr.y, acc.z + xr.z, acc.w + xr.w};
    float b[4] = {acc.x * xr.x, acc.y * xr.y, acc.z * xr.z, acc.w * xr.w};
    __nv_bfloat16 ha[4], la[4], hb[4], lb[4];
#pragma unroll
    for (int j = 0; j < 4; j++) { bf16_split(a[j], ha[j], la[j]); bf16_split(b[j], hb[j], lb[j]); }
    size_t base = (size_t)r * 256 + lane * 4;
    *(uint2*)(g_ah + base)        = *(uint2*)ha;
    *(uint2*)(g_ah + base + 128)  = *(uint2*)hb;
    *(uint2*)(g_al + base)        = *(uint2*)la;
    *(uint2*)(g_al + base + 128)  = *(uint2*)lb;
}

// ==================== mma.sync / cp.async helpers (baseline ISA) ====================
__device__ __forceinline__ uint32_t smem_u32(const void* p) {
    uint32_t a;
    asm("{ .reg .u64 t; cvta.to.shared.u64 t, %1; cvt.u32.u64 %0, t; }" : "=r"(a) : "l"(p));
    return a;
}
__device__ __forceinline__ void ldsm_x4(uint32_t* r, uint32_t addr) {
    asm volatile("ldmatrix.sync.aligned.m8n8.x4.shared.b16 {%0,%1,%2,%3}, [%4];"
                 : "=r"(r[0]), "=r"(r[1]), "=r"(r[2]), "=r"(r[3]) : "r"(addr));
}
__device__ __forceinline__ void ldsm_x4_t(uint32_t* r, uint32_t addr) {
    asm volatile("ldmatrix.sync.aligned.m8n8.x4.trans.shared.b16 {%0,%1,%2,%3}, [%4];"
                 : "=r"(r[0]), "=r"(r[1]), "=r"(r[2]), "=r"(r[3]) : "r"(addr));
}
__device__ __forceinline__ void mma_bf16(float* d, const uint32_t* a, const uint32_t* b) {
    asm volatile("mma.sync.aligned.m16n8k16.row.col.f32.bf16.bf16.f32 "
                 "{%0,%1,%2,%3}, {%4,%5,%6,%7}, {%8,%9}, {%0,%1,%2,%3};"
                 : "+f"(d[0]), "+f"(d[1]), "+f"(d[2]), "+f"(d[3])
                 : "r"(a[0]), "r"(a[1]), "r"(a[2]), "r"(a[3]), "r"(b[0]), "r"(b[1]));
}
__device__ __forceinline__ void cp16(uint32_t dst, const void* src, bool pred) {
    asm volatile("cp.async.cg.shared.global [%0], [%1], 16, %2;"
                 :: "r"(dst), "l"(src), "r"(pred ? 16u : 0u));
}
__device__ __forceinline__ void cp_commit() {
    asm volatile("cp.async.commit_group;" ::: "memory");
}

// ================= persistent pipelined bf16-split tensor-core dense layer =================
// B staged ONCE per block (persistent grid), A double-buffered per 128-row tile.
#define RSTRIDE_B 272
#define ASTRIDE 144
#define OFF_BH 0
#define OFF_BL (256 * RSTRIDE_B)                        // 69632
#define OFF_A  (2 * 256 * RSTRIDE_B)                    // 139264
#define ABUF(m, b) (OFF_A + (((b) * 2 + (m)) * 128 * ASTRIDE))
#define OFF_C  OFF_A                                    // 128*132*4 = 67584 <= 73728
#define GEMM_SMEM (OFF_A + 4 * 128 * ASTRIDE)           // 212992

__global__ void __launch_bounds__(256, 1) mma_gemm_kernel(float* __restrict__ out, int layer) {
    extern __shared__ char smem[];
    uint32_t sbase = smem_u32(smem);
    int tid = threadIdx.x;
    int wid = tid >> 5, lid = tid & 31;
    int warp_m = wid >> 2, warp_n = wid & 3;      // 2x4 warp grid: 64-row x 32-col warp tiles
    float4 bias4 = ((const float4*)(g_bias + layer * 128))[lid];

    // ---- stage B ONCE (group; resident for all tiles) ----
    {
        const char* gwh = (const char*)g_wbh + (size_t)layer * 65536;
        const char* gwl = (const char*)g_wbl + (size_t)layer * 65536;
        for (int i = tid; i < 8192; i += 256) {
            int m = i >> 12, rem = i & 4095, r = rem >> 4, q = rem & 15;
            uint32_t dst = sbase + (m ? OFF_BL : OFF_BH) + r * RSTRIDE_B + q * 16;
            const char* src = (m ? gwl : gwh) + r * 256 + q * 16;
            cp16(dst, src, true);
        }
        cp_commit();
    }

    auto stageA = [&](int c, int row0) {
        int buf = c & 1;
        const char* gah = (const char*)g_ah;
        const char* gal = (const char*)g_al;
#pragma unroll
        for (int it = 0; it < 8; it++) {
            int i = tid + it * 256;                // 0..2047
            int m = i >> 10, rem = i & 1023, r = rem >> 3, q = rem & 7;
            int gr = row0 + r;
            uint32_t dst = sbase + ABUF(m, buf) + r * ASTRIDE + q * 16;
            const char* src = (m ? gal : gah) + (size_t)gr * 512 + c * 128 + q * 16;
            cp16(dst, src, gr < N_NODES);
        }
        cp_commit();
    };

    // ---- persistent tile loop ----
    for (int tile = blockIdx.x; tile < N_TILES; tile += gridDim.x) {
        int row0 = tile * 128;
        __syncthreads();                     // prev epilogue's Cs reads complete
        stageA(0, row0);
        stageA(1, row0);

        float acc[4][4][4];
#pragma unroll
        for (int mf = 0; mf < 4; mf++)
#pragma unroll
            for (int nf = 0; nf < 4; nf++)
#pragma unroll
                for (int q = 0; q < 4; q++) acc[mf][nf][q] = 0.f;

#pragma unroll
        for (int c = 0; c < 4; c++) {
            if (c < 3) asm volatile("cp.async.wait_group 1;" ::: "memory");
            else       asm volatile("cp.async.wait_group 0;" ::: "memory");
            __syncthreads();

            int buf = c & 1;
            int kb = c * 64;
#pragma unroll
            for (int k16 = 0; k16 < 4; k16++) {
                int k0 = k16 * 16;
                uint32_t ah[4][4], al[4][4];
                int ar = (lid & 15);
                int ac = (k0 + ((lid >> 4) << 3)) * 2;
#pragma unroll
                for (int mf = 0; mf < 4; mf++) {
                    int r = warp_m * 64 + mf * 16 + ar;
                    ldsm_x4(ah[mf], sbase + ABUF(0, buf) + r * ASTRIDE + ac);
                    ldsm_x4(al[mf], sbase + ABUF(1, buf) + r * ASTRIDE + ac);
                }
                uint32_t bh[4][2], bl[4][2];
                int br = kb + k0 + (lid & 15);
#pragma unroll
                for (int np = 0; np < 2; np++) {
                    int nc = (warp_n * 32 + np * 16 + ((lid >> 4) << 3)) * 2;
                    uint32_t t[4];
                    ldsm_x4_t(t, sbase + OFF_BH + br * RSTRIDE_B + nc);
                    bh[np * 2][0] = t[0]; bh[np * 2][1] = t[1];
                    bh[np * 2 + 1][0] = t[2]; bh[np * 2 + 1][1] = t[3];
                    ldsm_x4_t(t, sbase + OFF_BL + br * RSTRIDE_B + nc);
                    bl[np * 2][0] = t[0]; bl[np * 2][1] = t[1];
                    bl[np * 2 + 1][0] = t[2]; bl[np * 2 + 1][1] = t[3];
                }
#pragma unroll
                for (int mf = 0; mf < 4; mf++)
#pragma unroll
                    for (int nf = 0; nf < 4; nf++) {
                        mma_bf16(acc[mf][nf], ah[mf], bh[nf]);  // hi*hi
                        mma_bf16(acc[mf][nf], ah[mf], bl[nf]);  // hi*lo
                        mma_bf16(acc[mf][nf], al[mf], bh[nf]);  // lo*hi
                    }
            }
            __syncthreads();       // all ldmatrix reads of this buffer done
            if (c + 2 < 4) stageA(c + 2, row0);
        }

        // ---- dump accumulators to SMEM C tile (aliases A buf 0) ----
        float* Cs = (float*)(smem + OFF_C);
#pragma unroll
        for (int mf = 0; mf < 4; mf++)
#pragma unroll
            for (int nf = 0; nf < 4; nf++) {
                int r = warp_m * 64 + mf * 16 + (lid >> 2);
                int cc = warp_n * 32 + nf * 8 + (lid & 3) * 2;
                *(float2*)&Cs[r * 132 + cc]       = make_float2(acc[mf][nf][0], acc[mf][nf][1]);
                *(float2*)&Cs[(r + 8) * 132 + cc] = make_float2(acc[mf][nf][2], acc[mf][nf][3]);
            }
        __syncthreads();

        // ---- epilogue: warp per row — bias + leaky + L2 norm + dual store ----
#pragma unroll
        for (int it = 0; it < 16; it++) {
            int row = it * 8 + wid;
            int gr = row0 + row;
            float4 v = *(float4*)&Cs[row * 132 + lid * 4];
            float t0 = v.x + bias4.x, t1 = v.y + bias4.y;
            float t2 = v.z + bias4.z, t3 = v.w + bias4.w;
            t0 = (t0 > 0.f) ? t0 : 0.01f * t0;
            t1 = (t1 > 0.f) ? t1 : 0.01f * t1;
            t2 = (t2 > 0.f) ? t2 : 0.01f * t2;
            t3 = (t3 > 0.f) ? t3 : 0.01f * t3;
            float ss = fmaf(t0, t0, fmaf(t1, t1, fmaf(t2, t2, t3 * t3)));
            ss += __shfl_xor_sync(0xffffffffu, ss, 16);
            ss += __shfl_xor_sync(0xffffffffu, ss, 8);
            ss += __shfl_xor_sync(0xffffffffu, ss, 4);
            ss += __shfl_xor_sync(0xffffffffu, ss, 2);
            ss += __shfl_xor_sync(0xffffffffu, ss, 1);
            float sc = 1.0f / fmaxf(sqrtf(ss), 1e-12f);
            if (gr < N_NODES) {
                float4 o = make_float4(t0 * sc, t1 * sc, t2 * sc, t3 * sc);
                ((float4*)&g_x[(size_t)gr * 128])[lid] = o;
                ((float4*)&out[(size_t)gr * 384 + (size_t)(layer + 1) * 128])[lid] = o;
            }
        }
    }
}

// ================= launch =================
extern "C" void kernel_launch(void* const* d_in, const int* in_sizes, int n_in,
                              void* d_out, int out_size) {
    const int*   adj_row  = (const int*)d_in[0];
    const int*   adj_col  = (const int*)d_in[1];
    const float* adj_vals = (const float*)d_in[2];
    const float* emb      = (const float*)d_in[3];
    const float* W1w      = (const float*)d_in[4];
    const float* W1b      = (const float*)d_in[5];
    const float* W2w      = (const float*)d_in[6];
    const float* W2b      = (const float*)d_in[7];
    float* out = (float*)d_out;

    cudaFuncSetAttribute(mma_gemm_kernel, cudaFuncAttributeMaxDynamicSharedMemorySize, GEMM_SMEM);

    setup_kernel<<<(SETUP_N + 255) / 256, 256>>>(emb, out, W1w, W1b, W2w, W2b, adj_row);
    bsum_kernel<<<NBLK, 256>>>();
    bscan_kernel<<<1, 512>>>();
    pscan_kernel<<<NBLK, 256>>>();
    scatter_kernel<<<(NNZ + 255) / 256, 256>>>(adj_row, adj_col, adj_vals);

    const int gather_blocks = (N_NODES * 32 + 255) / 256;   // warp per row

    for (int layer = 0; layer < 2; layer++) {
        gather_kernel<<<gather_blocks, 256>>>();
        mma_gemm_kernel<<<GEMM_GRID, 256, GEMM_SMEM>>>(out, layer);
    }
}